// round 7
// baseline (speedup 1.0000x reference)
#include <cuda_runtime.h>
#include <cuda_bf16.h>

#define BATCH   16384
#define EMBED   64
#define N_EDGES 524288
#define FULL    0xffffffffu

// Scratch (device globals — zero-initialized at module load; the MLP kernel
// re-zeroes them after consuming, so EVERY launch begins with zeros).
__device__ float g_acc[BATCH * EMBED];   // 4 MB segment sums
__device__ float g_cnt[BATCH];           // segment counts

// ---------------------------------------------------------------------------
// Kernel 1: edge aggregation (R2 design — proven best). Warp owns 32
// consecutive edges; ids coalesced + shfl-broadcast; 8 independent 256B
// feature-row loads in flight; register run-compression on sorted seg_ids,
// atomic flush only on segment change.
// ---------------------------------------------------------------------------
__global__ void agg_kernel(const int*   __restrict__ neigh_ids,
                           const int*   __restrict__ seg_ids,
                           const float* __restrict__ features) {
    const int warp = (blockIdx.x * blockDim.x + threadIdx.x) >> 5;
    const int lane = threadIdx.x & 31;
    const int e0 = warp * 32;
    if (e0 >= N_EDGES) return;

    const int my_seg = seg_ids[e0 + lane];
    const int my_nid = neigh_ids[e0 + lane];

    const float2* __restrict__ feats2 = (const float2*)features;

    float2 acc = make_float2(0.0f, 0.0f);
    int cur = __shfl_sync(FULL, my_seg, 0);
    int runlen = 0;

    #pragma unroll
    for (int c = 0; c < 32; c += 8) {
        int    n[8], s[8];
        float2 v[8];
        #pragma unroll
        for (int u = 0; u < 8; ++u) n[u] = __shfl_sync(FULL, my_nid, c + u);
        #pragma unroll
        for (int u = 0; u < 8; ++u) v[u] = feats2[(size_t)n[u] * 32 + lane];
        #pragma unroll
        for (int u = 0; u < 8; ++u) s[u] = __shfl_sync(FULL, my_seg, c + u);
        #pragma unroll
        for (int u = 0; u < 8; ++u) {
            if (s[u] != cur) {            // warp-uniform (s is broadcast)
                atomicAdd(&g_acc[cur * EMBED + 2 * lane],     acc.x);
                atomicAdd(&g_acc[cur * EMBED + 2 * lane + 1], acc.y);
                if (lane == 0) atomicAdd(&g_cnt[cur], (float)runlen);
                acc = make_float2(0.0f, 0.0f);
                cur = s[u];
                runlen = 0;
            }
            acc.x += v[u].x;
            acc.y += v[u].y;
            ++runlen;
        }
    }
    atomicAdd(&g_acc[cur * EMBED + 2 * lane],     acc.x);
    atomicAdd(&g_acc[cur * EMBED + 2 * lane + 1], acc.y);
    if (lane == 0) atomicAdd(&g_cnt[cur], (float)runlen);
}

// ---------------------------------------------------------------------------
// Kernel 2: self gather + mean + [self|neigh] @ w1^T + b1, relu — and
// CONSUMER-ZEROING of g_acc/g_cnt (each element read once, then reset, so
// the next launch/replay starts from zeros without a zero kernel).
// Register-tiled weights + packed f32x2 FMA (R5 design).
// ---------------------------------------------------------------------------
__global__ void mlp_kernel(const int*   __restrict__ nodes,
                           const float* __restrict__ features,
                           const float* __restrict__ w1,
                           const float* __restrict__ b1,
                           float*       __restrict__ out) {
    __shared__ float w1s[64 * 129];                 // padded stage of w1
    __shared__ float b1s[64];
    __shared__ __align__(16) float comb[4][128];    // 4 rows of concat
    __shared__ float part[4][64 * 5];               // stride-5 padded partials

    for (int idx = threadIdx.x; idx < 64 * 128; idx += blockDim.x) {
        const int j = idx >> 7;
        const int k = idx & 127;
        w1s[j * 129 + k] = w1[idx];                 // w1 row-major (64,128)
    }
    if (threadIdx.x < 64) b1s[threadIdx.x] = b1[threadIdx.x];
    __syncthreads();

    const int g = threadIdx.x >> 6;                 // k-group 0..3
    const int j = threadIdx.x & 63;                 // output dim

    // packed weight pairs: w2[kk] = {w1[j][g*32+2kk], w1[j][g*32+2kk+1]}
    unsigned long long w2[16];
    #pragma unroll
    for (int kk = 0; kk < 16; ++kk) {
        const float lo = w1s[j * 129 + g * 32 + 2 * kk];
        const float hi = w1s[j * 129 + g * 32 + 2 * kk + 1];
        asm("mov.b64 %0, {%1, %2};" : "=l"(w2[kk]) : "f"(lo), "f"(hi));
    }

    const int r = threadIdx.x >> 6;                 // row for fill/writeback
    for (int base = blockIdx.x * 4; base < BATCH; base += gridDim.x * 4) {
        const int b = base + r;
        {
            const int node = nodes[b];
            comb[r][j]      = features[(size_t)node * EMBED + j];
            const float a   = g_acc[b * EMBED + j]; // sole reader of this elem
            g_acc[b * EMBED + j] = 0.0f;            // reset for next launch
            const float inv = 1.0f / fmaxf(g_cnt[b], 1.0f);
            comb[r][64 + j] = a * inv;
        }
        __syncthreads();                            // all g_cnt[b] reads done
        if (j == 0) g_cnt[b] = 0.0f;                // reset for next launch

        #pragma unroll
        for (int rr = 0; rr < 4; ++rr) {
            const ulonglong2* c2 = (const ulonglong2*)&comb[rr][g * 32];
            unsigned long long acc = 0ull;          // packed {0.f, 0.f}
            #pragma unroll
            for (int q = 0; q < 8; ++q) {           // 8 x LDS.128 broadcast
                const ulonglong2 c = c2[q];
                asm("fma.rn.f32x2 %0, %1, %2, %0;"
                    : "+l"(acc) : "l"(c.x), "l"(w2[2 * q]));
                asm("fma.rn.f32x2 %0, %1, %2, %0;"
                    : "+l"(acc) : "l"(c.y), "l"(w2[2 * q + 1]));
            }
            float lo, hi;
            asm("mov.b64 {%0, %1}, %2;" : "=f"(lo), "=f"(hi) : "l"(acc));
            part[rr][j * 5 + g] = lo + hi;          // conflict-free (5⊥32)
        }
        __syncthreads();

        {
            const float s = part[r][j * 5 + 0] + part[r][j * 5 + 1] +
                            part[r][j * 5 + 2] + part[r][j * 5 + 3] + b1s[j];
            out[(size_t)b * EMBED + j] = fmaxf(s, 0.0f);
        }
        __syncthreads();
    }
}

// ---------------------------------------------------------------------------
// Launch — two kernels, no zero kernel (consumer-zeroing keeps scratch clean
// across graph replays; module load provides the initial zeros).
// inputs: nodes(i32,16384) neigh_ids(i32,524288) seg_ids(i32,524288)
//         features(f32,64M) w1(f32,8192) b1(f32,64)   output: f32 (16384,64)
// ---------------------------------------------------------------------------
extern "C" void kernel_launch(void* const* d_in, const int* in_sizes, int n_in,
                              void* d_out, int out_size) {
    const int*   nodes     = (const int*)  d_in[0];
    const int*   neigh_ids = (const int*)  d_in[1];
    const int*   seg_ids   = (const int*)  d_in[2];
    const float* features  = (const float*)d_in[3];
    const float* w1        = (const float*)d_in[4];
    const float* b1        = (const float*)d_in[5];
    float*       out       = (float*)d_out;

    const int n_warps = N_EDGES / 32;             // 16384 warps
    agg_kernel<<<n_warps / 8, 256>>>(neigh_ids, seg_ids, features);

    mlp_kernel<<<444, 256>>>(nodes, features, w1, b1, out);
}

// round 8
// speedup vs baseline: 1.1289x; 1.1289x over previous
#include <cuda_runtime.h>
#include <cuda_bf16.h>

#define BATCH   16384
#define EMBED   64
#define N_EDGES 524288
#define FULL    0xffffffffu
#define EPW     128          // edges per warp (amortize boundary atomics)

// Scratch (device globals — no allocation allowed)
__device__ float g_acc[BATCH * EMBED];   // 4 MB segment sums
__device__ float g_cnt[BATCH];           // segment counts

// ---------------------------------------------------------------------------
// Kernel 1: zero accumulators (float4)
// ---------------------------------------------------------------------------
__global__ void zero_kernel() {
    const int i = blockIdx.x * blockDim.x + threadIdx.x;
    const float4 z = make_float4(0.f, 0.f, 0.f, 0.f);
    if (i < 262144)       ((float4*)g_acc)[i] = z;
    else if (i < 266240)  ((float4*)g_cnt)[i - 262144] = z;
}

// ---------------------------------------------------------------------------
// Kernel 2: edge aggregation. Warp owns 128 consecutive sorted edges.
// Segments strictly inside (firstSeg, lastSeg) are fully contained in this
// warp's range -> complete sums -> plain STG (no atomic, relies on zeros only
// for untouched/empty segments). Only the <=2 boundary segments use atomics.
// This cuts element-atomics ~5x vs 32-edges-per-warp.
// Gather: ids coalesced + shfl broadcast, 8 independent 256B row loads in
// flight, register run-compression on the sorted seg_ids.
// ---------------------------------------------------------------------------
__global__ void agg_kernel(const int*   __restrict__ neigh_ids,
                           const int*   __restrict__ seg_ids,
                           const float* __restrict__ features) {
    const int warp = (blockIdx.x * blockDim.x + threadIdx.x) >> 5;
    const int lane = threadIdx.x & 31;
    const int e0 = warp * EPW;
    if (e0 >= N_EDGES) return;

    // uniform scalar loads (L1 broadcast): boundary segment ids of this warp
    const int firstSeg = seg_ids[e0];
    const int lastSeg  = seg_ids[e0 + EPW - 1];

    const float2* __restrict__ feats2 = (const float2*)features;

    float2 acc = make_float2(0.0f, 0.0f);
    int cur = firstSeg;
    int runlen = 0;

    #pragma unroll
    for (int chunk = 0; chunk < EPW; chunk += 32) {
        const int base = e0 + chunk;
        const int my_seg = seg_ids[base + lane];     // coalesced
        const int my_nid = neigh_ids[base + lane];

        #pragma unroll
        for (int c = 0; c < 32; c += 8) {
            int    n[8], s[8];
            float2 v[8];
            #pragma unroll
            for (int u = 0; u < 8; ++u) n[u] = __shfl_sync(FULL, my_nid, c + u);
            #pragma unroll
            for (int u = 0; u < 8; ++u) v[u] = feats2[(size_t)n[u] * 32 + lane];
            #pragma unroll
            for (int u = 0; u < 8; ++u) s[u] = __shfl_sync(FULL, my_seg, c + u);
            #pragma unroll
            for (int u = 0; u < 8; ++u) {
                if (s[u] != cur) {          // warp-uniform (s is broadcast)
                    if (cur > firstSeg && cur < lastSeg) {
                        // fully-contained segment: complete sum, plain store
                        ((float2*)g_acc)[(size_t)cur * 32 + lane] = acc;
                        if (lane == 0) g_cnt[cur] = (float)runlen;
                    } else {
                        atomicAdd(&g_acc[cur * EMBED + 2 * lane],     acc.x);
                        atomicAdd(&g_acc[cur * EMBED + 2 * lane + 1], acc.y);
                        if (lane == 0) atomicAdd(&g_cnt[cur], (float)runlen);
                    }
                    acc = make_float2(0.0f, 0.0f);
                    cur = s[u];
                    runlen = 0;
                }
                acc.x += v[u].x;
                acc.y += v[u].y;
                ++runlen;
            }
        }
    }
    // final flush: cur is a boundary segment (== lastSeg) -> atomic
    atomicAdd(&g_acc[cur * EMBED + 2 * lane],     acc.x);
    atomicAdd(&g_acc[cur * EMBED + 2 * lane + 1], acc.y);
    if (lane == 0) atomicAdd(&g_cnt[cur], (float)runlen);
}

// ---------------------------------------------------------------------------
// Kernel 3 (R5 — proven): self gather + mean + [self|neigh] @ w1^T + b1, relu.
// Register-tiled weights + packed f32x2 FMA.
// ---------------------------------------------------------------------------
__global__ void mlp_kernel(const int*   __restrict__ nodes,
                           const float* __restrict__ features,
                           const float* __restrict__ w1,
                           const float* __restrict__ b1,
                           float*       __restrict__ out) {
    __shared__ float w1s[64 * 129];                 // padded stage of w1
    __shared__ float b1s[64];
    __shared__ __align__(16) float comb[4][128];    // 4 rows of concat
    __shared__ float part[4][64 * 5];               // stride-5 padded partials

    for (int idx = threadIdx.x; idx < 64 * 128; idx += blockDim.x) {
        const int j = idx >> 7;
        const int k = idx & 127;
        w1s[j * 129 + k] = w1[idx];                 // w1 row-major (64,128)
    }
    if (threadIdx.x < 64) b1s[threadIdx.x] = b1[threadIdx.x];
    __syncthreads();

    const int g = threadIdx.x >> 6;                 // k-group 0..3
    const int j = threadIdx.x & 63;                 // output dim

    unsigned long long w2[16];
    #pragma unroll
    for (int kk = 0; kk < 16; ++kk) {
        const float lo = w1s[j * 129 + g * 32 + 2 * kk];
        const float hi = w1s[j * 129 + g * 32 + 2 * kk + 1];
        asm("mov.b64 %0, {%1, %2};" : "=l"(w2[kk]) : "f"(lo), "f"(hi));
    }

    const int r = threadIdx.x >> 6;                 // row for fill/writeback
    for (int base = blockIdx.x * 4; base < BATCH; base += gridDim.x * 4) {
        {
            const int b = base + r;
            const int node = nodes[b];
            comb[r][j]      = features[(size_t)node * EMBED + j];
            const float inv = 1.0f / fmaxf(g_cnt[b], 1.0f);
            comb[r][64 + j] = g_acc[b * EMBED + j] * inv;
        }
        __syncthreads();

        #pragma unroll
        for (int rr = 0; rr < 4; ++rr) {
            const ulonglong2* c2 = (const ulonglong2*)&comb[rr][g * 32];
            unsigned long long acc = 0ull;          // packed {0.f, 0.f}
            #pragma unroll
            for (int q = 0; q < 8; ++q) {           // 8 x LDS.128 broadcast
                const ulonglong2 c = c2[q];
                asm("fma.rn.f32x2 %0, %1, %2, %0;"
                    : "+l"(acc) : "l"(c.x), "l"(w2[2 * q]));
                asm("fma.rn.f32x2 %0, %1, %2, %0;"
                    : "+l"(acc) : "l"(c.y), "l"(w2[2 * q + 1]));
            }
            float lo, hi;
            asm("mov.b64 {%0, %1}, %2;" : "=f"(lo), "=f"(hi) : "l"(acc));
            part[rr][j * 5 + g] = lo + hi;          // conflict-free (5⊥32)
        }
        __syncthreads();

        {
            const int b = base + r;
            const float s = part[r][j * 5 + 0] + part[r][j * 5 + 1] +
                            part[r][j * 5 + 2] + part[r][j * 5 + 3] + b1s[j];
            out[(size_t)b * EMBED + j] = fmaxf(s, 0.0f);
        }
        __syncthreads();
    }
}

// ---------------------------------------------------------------------------
// Launch
// inputs: nodes(i32,16384) neigh_ids(i32,524288) seg_ids(i32,524288)
//         features(f32,64M) w1(f32,8192) b1(f32,64)   output: f32 (16384,64)
// ---------------------------------------------------------------------------
extern "C" void kernel_launch(void* const* d_in, const int* in_sizes, int n_in,
                              void* d_out, int out_size) {
    const int*   nodes     = (const int*)  d_in[0];
    const int*   neigh_ids = (const int*)  d_in[1];
    const int*   seg_ids   = (const int*)  d_in[2];
    const float* features  = (const float*)d_in[3];
    const float* w1        = (const float*)d_in[4];
    const float* b1        = (const float*)d_in[5];
    float*       out       = (float*)d_out;

    zero_kernel<<<(266240 + 255) / 256, 256>>>();

    const int n_warps = N_EDGES / EPW;            // 4096 warps
    agg_kernel<<<n_warps / 8, 256>>>(neigh_ids, seg_ids, features);

    mlp_kernel<<<444, 256>>>(nodes, features, w1, b1, out);
}

// round 9
// speedup vs baseline: 1.3428x; 1.1894x over previous
#include <cuda_runtime.h>
#include <cuda_bf16.h>

#define BATCH   16384
#define EMBED   64
#define N_EDGES 524288
#define FULL    0xffffffffu
#define MLPGRID 592

// One fused scratch symbol so a single cudaMemsetAsync (graph memset node,
// no kernel-launch floor) zeroes everything. Layout: [acc 4MB | cnt 64KB].
__device__ float g_scratch[BATCH * EMBED + BATCH];
#define G_ACC g_scratch
#define G_CNT (g_scratch + BATCH * EMBED)

// ---------------------------------------------------------------------------
// Kernel 1: edge aggregation (R2 design — proven best) + cache-path hints.
// Warp owns 32 consecutive edges; ids coalesced (streaming .cs) and shfl-
// broadcast; 8 independent 256B feature-row loads in flight via .cg (bypass
// L1 — random rows have no L1 reuse); register run-compression on sorted
// seg_ids, atomic flush only on segment change.
// ---------------------------------------------------------------------------
__global__ void agg_kernel(const int*   __restrict__ neigh_ids,
                           const int*   __restrict__ seg_ids,
                           const float* __restrict__ features) {
    const int warp = (blockIdx.x * blockDim.x + threadIdx.x) >> 5;
    const int lane = threadIdx.x & 31;
    const int e0 = warp * 32;
    if (e0 >= N_EDGES) return;

    const int my_seg = __ldcs(&seg_ids[e0 + lane]);    // streamed once
    const int my_nid = __ldcs(&neigh_ids[e0 + lane]);

    const float2* __restrict__ feats2 = (const float2*)features;

    float2 acc = make_float2(0.0f, 0.0f);
    int cur = __shfl_sync(FULL, my_seg, 0);
    int runlen = 0;

    #pragma unroll
    for (int c = 0; c < 32; c += 8) {
        int    n[8], s[8];
        float2 v[8];
        #pragma unroll
        for (int u = 0; u < 8; ++u) n[u] = __shfl_sync(FULL, my_nid, c + u);
        #pragma unroll
        for (int u = 0; u < 8; ++u)
            v[u] = __ldcg(&feats2[(size_t)n[u] * 32 + lane]);  // L2-only
        #pragma unroll
        for (int u = 0; u < 8; ++u) s[u] = __shfl_sync(FULL, my_seg, c + u);
        #pragma unroll
        for (int u = 0; u < 8; ++u) {
            if (s[u] != cur) {            // warp-uniform (s is broadcast)
                atomicAdd(&G_ACC[cur * EMBED + 2 * lane],     acc.x);
                atomicAdd(&G_ACC[cur * EMBED + 2 * lane + 1], acc.y);
                if (lane == 0) atomicAdd(&G_CNT[cur], (float)runlen);
                acc = make_float2(0.0f, 0.0f);
                cur = s[u];
                runlen = 0;
            }
            acc.x += v[u].x;
            acc.y += v[u].y;
            ++runlen;
        }
    }
    atomicAdd(&G_ACC[cur * EMBED + 2 * lane],     acc.x);
    atomicAdd(&G_ACC[cur * EMBED + 2 * lane + 1], acc.y);
    if (lane == 0) atomicAdd(&G_CNT[cur], (float)runlen);
}

// ---------------------------------------------------------------------------
// Kernel 2: self gather + mean + [self|neigh] @ w1^T + b1, relu.
// Register-tiled weights + packed f32x2 FMA (R5) PLUS:
//   - cross-iteration software pipeline: node ids / counts staged 2 iters
//     ahead, feature/acc rows 1 iter ahead into a double-buffered comb, so
//     the dependent nodes->features gather chain overlaps the FMA block.
//   - smem reuse: w1 staging buffer is only needed to fill the weight
//     registers, so it shares storage with the run-phase buffers (union)
//     -> ~34KB/block -> 4 blocks/SM at grid 592.
// ---------------------------------------------------------------------------
__global__ void __launch_bounds__(256)
mlp_kernel(const int*   __restrict__ nodes,
           const float* __restrict__ features,
           const float* __restrict__ w1,
           const float* __restrict__ b1,
           float*       __restrict__ out) {
    __shared__ union {
        float w1s[64 * 129];                        // staging (prologue only)
        struct {
            __align__(16) float comb[2][4][128];    // double-buffered concat
            float part[4][64 * 5];                  // stride-5 padded partials
        } run;
    } sm;
    __shared__ float b1s[64];

    const int tid = threadIdx.x;
    const int g = tid >> 6;                         // k-group 0..3
    const int j = tid & 63;                         // output dim
    const int r = g;                                // row for fill/writeback

    // ---- prologue: stage w1, fill weight registers, then release w1s ----
    for (int idx = tid; idx < 64 * 128; idx += 256) {
        const int jj = idx >> 7;
        const int kk = idx & 127;
        sm.w1s[jj * 129 + kk] = w1[idx];            // w1 row-major (64,128)
    }
    if (tid < 64) b1s[tid] = b1[tid];
    __syncthreads();

    unsigned long long w2[16];
    #pragma unroll
    for (int kk = 0; kk < 16; ++kk) {
        const float lo = sm.w1s[j * 129 + g * 32 + 2 * kk];
        const float hi = sm.w1s[j * 129 + g * 32 + 2 * kk + 1];
        asm("mov.b64 %0, {%1, %2};" : "=l"(w2[kk]) : "f"(lo), "f"(hi));
    }
    __syncthreads();                                // w1s dead; union reused

    const int stride = MLPGRID * 4;
    const int base0  = blockIdx.x * 4;

    // pipeline regs: nodeA/cntA belong to iter i+1
    int   nodeA = 0;
    float cntA  = 1.0f;

    // fill comb[0] for iter 0; stage ids for iter 1
    {
        const int b  = base0 + r;
        const int nd = nodes[b];
        const float c = G_CNT[b];
        sm.run.comb[0][r][j]      = __ldcg(&features[(size_t)nd * EMBED + j]);
        sm.run.comb[0][r][64 + j] = G_ACC[b * EMBED + j] * (1.0f / fmaxf(c, 1.0f));
        const int base1 = base0 + stride;
        if (base1 < BATCH) {
            nodeA = nodes[base1 + r];
            cntA  = G_CNT[base1 + r];
        }
    }
    __syncthreads();

    int cur = 0;
    for (int base = base0; base < BATCH; base += stride) {
        const int base1 = base + stride;
        const int base2 = base + 2 * stride;

        // issue next-iter feature/acc loads (overlap with FMA block below)
        float fN = 0.0f, aN = 0.0f;
        if (base1 < BATCH) {
            fN = __ldcg(&features[(size_t)nodeA * EMBED + j]);
            aN = G_ACC[(base1 + r) * EMBED + j] * (1.0f / fmaxf(cntA, 1.0f));
        }
        // issue next-next-iter id/cnt loads
        int   nodeB = 0;
        float cntB  = 1.0f;
        if (base2 < BATCH) {
            nodeB = nodes[base2 + r];
            cntB  = G_CNT[base2 + r];
        }

        // compute partials from comb[cur] (packed f32x2 FMA)
        #pragma unroll
        for (int rr = 0; rr < 4; ++rr) {
            const ulonglong2* c2 = (const ulonglong2*)&sm.run.comb[cur][rr][g * 32];
            unsigned long long acc = 0ull;          // packed {0.f, 0.f}
            #pragma unroll
            for (int q = 0; q < 8; ++q) {           // 8 x LDS.128 broadcast
                const ulonglong2 c = c2[q];
                asm("fma.rn.f32x2 %0, %1, %2, %0;"
                    : "+l"(acc) : "l"(c.x), "l"(w2[2 * q]));
                asm("fma.rn.f32x2 %0, %1, %2, %0;"
                    : "+l"(acc) : "l"(c.y), "l"(w2[2 * q + 1]));
            }
            float lo, hi;
            asm("mov.b64 {%0, %1}, %2;" : "=f"(lo), "=f"(hi) : "l"(acc));
            sm.run.part[rr][j * 5 + g] = lo + hi;   // conflict-free (5⊥32)
        }
        __syncthreads();

        // reduce + bias + relu + store (thread (r, j) owns row base+r)
        {
            const float s = sm.run.part[r][j * 5 + 0] + sm.run.part[r][j * 5 + 1] +
                            sm.run.part[r][j * 5 + 2] + sm.run.part[r][j * 5 + 3] +
                            b1s[j];
            out[(size_t)(base + r) * EMBED + j] = fmaxf(s, 0.0f);
        }
        // stage next iteration's comb into the other buffer
        if (base1 < BATCH) {
            sm.run.comb[cur ^ 1][r][j]      = fN;
            sm.run.comb[cur ^ 1][r][64 + j] = aN;
        }
        nodeA = nodeB;
        cntA  = cntB;
        __syncthreads();
        cur ^= 1;
    }
}

// ---------------------------------------------------------------------------
// Launch — memset node (no zero-kernel launch floor) + 2 kernels.
// inputs: nodes(i32,16384) neigh_ids(i32,524288) seg_ids(i32,524288)
//         features(f32,64M) w1(f32,8192) b1(f32,64)   output: f32 (16384,64)
// ---------------------------------------------------------------------------
extern "C" void kernel_launch(void* const* d_in, const int* in_sizes, int n_in,
                              void* d_out, int out_size) {
    const int*   nodes     = (const int*)  d_in[0];
    const int*   neigh_ids = (const int*)  d_in[1];
    const int*   seg_ids   = (const int*)  d_in[2];
    const float* features  = (const float*)d_in[3];
    const float* w1        = (const float*)d_in[4];
    const float* b1        = (const float*)d_in[5];
    float*       out       = (float*)d_out;

    void* scratch_ptr = nullptr;
    cudaGetSymbolAddress(&scratch_ptr, g_scratch);
    cudaMemsetAsync(scratch_ptr, 0,
                    (size_t)(BATCH * EMBED + BATCH) * sizeof(float), 0);

    const int n_warps = N_EDGES / 32;             // 16384 warps
    agg_kernel<<<n_warps / 8, 256>>>(neigh_ids, seg_ids, features);

    mlp_kernel<<<MLPGRID, 256>>>(nodes, features, w1, b1, out);
}